// round 8
// baseline (speedup 1.0000x reference)
#include <cuda_runtime.h>
#include <math.h>
#include <stdint.h>

// ---------------------------------------------------------------------------
// NanoGPT forward — round 7: tf32 mma.sync, 64x64 warp tile (128 thr/CTA),
// ldmatrix feeding, CVTB logits (no enc rounding pass), float4 LN/softmax.
// ---------------------------------------------------------------------------

#define D_MODEL 1024
#define SEQ_T   1024
#define BATCH   4
#define ROWS    (BATCH * SEQ_T)
#define VOCAB   32000
#define NLAYERS 6
#define LOGITS_ELEMS ((long long)ROWS * VOCAB)

// ---- scratch ----
__device__ float g_z[ROWS * D_MODEL];
__device__ float g_y[ROWS * D_MODEL];
__device__ float g_q[ROWS * D_MODEL];
__device__ float g_k[ROWS * D_MODEL];
__device__ float g_vT[D_MODEL * ROWS];          // v transposed: [d][b*T+t]
__device__ float g_s[BATCH * SEQ_T * SEQ_T];
__device__ float g_h[ROWS * D_MODEL];
__device__ float g_o[ROWS * D_MODEL];
__device__ float g_nll[ROWS];
__device__ float g_wqT[D_MODEL * D_MODEL];
__device__ float g_wkT[D_MODEL * D_MODEL];
__device__ float g_wvT[D_MODEL * D_MODEL];
__device__ float g_w1T[D_MODEL * D_MODEL];
__device__ float g_w2T[D_MODEL * D_MODEL];

__device__ __forceinline__ float rnd_tf32(float x) {
    uint32_t u;
    asm("cvt.rna.tf32.f32 %0, %1;" : "=r"(u) : "f"(x));
    return __uint_as_float(u);
}
__device__ __forceinline__ uint32_t cvt_bits(uint32_t x) {
    uint32_t u;
    asm("cvt.rna.tf32.f32 %0, %1;" : "=r"(u) : "f"(__uint_as_float(x)));
    return u;
}

__device__ __forceinline__ void mma_tf32(float c[4], const uint32_t a[4],
                                         const uint32_t b[2]) {
    asm volatile(
        "mma.sync.aligned.m16n8k8.row.col.f32.tf32.tf32.f32 "
        "{%0,%1,%2,%3}, {%4,%5,%6,%7}, {%8,%9}, {%0,%1,%2,%3};\n"
        : "+f"(c[0]), "+f"(c[1]), "+f"(c[2]), "+f"(c[3])
        : "r"(a[0]), "r"(a[1]), "r"(a[2]), "r"(a[3]), "r"(b[0]), "r"(b[1]));
}

__device__ __forceinline__ void ldsm4(uint32_t r[4], uint32_t addr) {
    asm volatile("ldmatrix.sync.aligned.m8n8.x4.shared.b16 {%0,%1,%2,%3}, [%4];"
                 : "=r"(r[0]), "=r"(r[1]), "=r"(r[2]), "=r"(r[3]) : "r"(addr));
}

__device__ __forceinline__ void cpa16s(uint32_t saddr, const float* g) {
    asm volatile("cp.async.cg.shared.global [%0], [%1], 16;\n" :: "r"(saddr), "l"(g));
}

#define STAGES 3
#define STAGE_WORDS 9216                 // A 128*36 + B 128*36
#define TRANS_BUF_WORDS (128 * 136)
#define GEMM_SMEM_BYTES (STAGES * STAGE_WORDS * 4)   // 110592 > trans buf

// ---------------------------------------------------------------------------
// tf32 tensor GEMM, NT only: C[M,N] = alpha * A[M,K] @ B[N,K]^T.
// Block 128x128x32, 128 threads, 4 warps (2m x 2n), warp tile 64x64.
// 3-stage cp.async ring; fragments via ldmatrix.x4 (per kb: 4 A-LDSM + 4
// B-LDSM feed 32 MMA). CVTB: round B fragments post-LDSM (raw fp32 B input).
// TRANS: writes C^T via smem-staged transpose.
// ---------------------------------------------------------------------------
template <bool BIAS, bool RELU, bool RES, bool ROUND, bool TRANS, bool CVTB>
__global__ __launch_bounds__(128, 2)
void tgemm(const float* __restrict__ A, const float* __restrict__ B,
           float* __restrict__ C, const float* __restrict__ bias,
           const float* __restrict__ res,
           int K, int lda, int ldb, int ldc, float alpha,
           long long sA, long long sB, long long sC)
{
    extern __shared__ float smem[];

    A += (long long)blockIdx.z * sA;
    B += (long long)blockIdx.z * sB;
    C += (long long)blockIdx.z * sC;
    const float* resp = RES ? (res + (long long)blockIdx.z * sC) : nullptr;

    const int tid  = threadIdx.x;
    const int lane = tid & 31;
    const int warp = tid >> 5;
    const int wm   = (warp & 1) * 64;
    const int wn   = (warp >> 1) * 64;
    const int q    = lane & 3;
    const int g    = lane >> 2;
    const long long m0 = (long long)blockIdx.y * 128;
    const long long n0 = (long long)blockIdx.x * 128;

    const uint32_t smem_u = (uint32_t)__cvta_generic_to_shared(smem);

    // producer map: rows tid>>2 (+32*s), 2 float4 chunks at (tid&3)*8
    const int prow = tid >> 2;
    const int pk8  = (tid & 3) * 8;

    // ldmatrix per-lane word offsets
    const uint32_t aw = (uint32_t)((wm + (lane & 15)) * 36 + ((lane >> 4) & 1) * 4);
    const uint32_t bw = (uint32_t)(4608 +
        (wn + ((lane >> 4) & 1) * 8 + (lane & 7)) * 36 + ((lane >> 3) & 1) * 4);

    float acc[4][8][4];
#pragma unroll
    for (int mt = 0; mt < 4; ++mt)
#pragma unroll
        for (int nt = 0; nt < 8; ++nt)
#pragma unroll
            for (int i = 0; i < 4; ++i) acc[mt][nt][i] = 0.f;

    auto LOAD = [&](int stage, int k0) {
        const uint32_t sb = smem_u + stage * (STAGE_WORDS * 4);
#pragma unroll
        for (int s = 0; s < 4; ++s) {
            const long long ra = (m0 + prow + 32 * s) * (long long)lda + k0 + pk8;
            const uint32_t  sa = sb + ((prow + 32 * s) * 36 + pk8) * 4;
            cpa16s(sa, A + ra);
            cpa16s(sa + 16, A + ra + 4);
        }
#pragma unroll
        for (int s = 0; s < 4; ++s) {
            const long long rb = (n0 + prow + 32 * s) * (long long)ldb + k0 + pk8;
            const uint32_t  sbb = sb + (4608 + (prow + 32 * s) * 36 + pk8) * 4;
            cpa16s(sbb, B + rb);
            cpa16s(sbb + 16, B + rb + 4);
        }
    };

    auto COMP = [&](int stage) {
        const uint32_t sb = smem_u + stage * (STAGE_WORDS * 4);
#pragma unroll
        for (int kb = 0; kb < 4; ++kb) {
            uint32_t af[4][4], bf[8][2];
#pragma unroll
            for (int mt = 0; mt < 4; ++mt)
                ldsm4(af[mt], sb + (aw + mt * 576 + kb * 8) * 4);
#pragma unroll
            for (int tp = 0; tp < 4; ++tp) {
                uint32_t r[4];
                ldsm4(r, sb + (bw + tp * 576 + kb * 8) * 4);
                if (CVTB) {
                    r[0] = cvt_bits(r[0]); r[1] = cvt_bits(r[1]);
                    r[2] = cvt_bits(r[2]); r[3] = cvt_bits(r[3]);
                }
                bf[tp * 2][0] = r[0]; bf[tp * 2][1] = r[1];
                bf[tp * 2 + 1][0] = r[2]; bf[tp * 2 + 1][1] = r[3];
            }
#pragma unroll
            for (int mt = 0; mt < 4; ++mt)
#pragma unroll
                for (int nt = 0; nt < 8; ++nt)
                    mma_tf32(acc[mt][nt], af[mt], bf[nt]);
        }
    };

    const int T = K >> 5;
    LOAD(0, 0);
    asm volatile("cp.async.commit_group;\n");
    if (T > 1) LOAD(1, 32);
    asm volatile("cp.async.commit_group;\n");

    int st = 0;
    for (int i = 0; i < T; ++i) {
        asm volatile("cp.async.wait_group 1;\n");
        __syncthreads();
        if (i + 2 < T) {
            int ns = st + 2; if (ns >= STAGES) ns -= STAGES;
            LOAD(ns, (i + 2) << 5);
        }
        asm volatile("cp.async.commit_group;\n");
        COMP(st);
        if (++st == STAGES) st = 0;
    }

    // ---- epilogue ----
    if (!TRANS) {
#pragma unroll
        for (int mt = 0; mt < 4; ++mt) {
            const long long r0 = m0 + wm + mt * 16 + g;
            const long long r1 = r0 + 8;
#pragma unroll
            for (int nt = 0; nt < 8; ++nt) {
                const long long col = n0 + wn + nt * 8 + 2 * q;
                float v0 = acc[mt][nt][0] * alpha;
                float v1 = acc[mt][nt][1] * alpha;
                float v2 = acc[mt][nt][2] * alpha;
                float v3 = acc[mt][nt][3] * alpha;
                if (BIAS) {
                    const float bb0 = bias[col], bb1 = bias[col + 1];
                    v0 += bb0; v1 += bb1; v2 += bb0; v3 += bb1;
                }
                if (RELU) {
                    v0 = fmaxf(v0, 0.f); v1 = fmaxf(v1, 0.f);
                    v2 = fmaxf(v2, 0.f); v3 = fmaxf(v3, 0.f);
                }
                if (RES) {
                    const float2 q0 = *(const float2*)(resp + r0 * ldc + col);
                    const float2 q1 = *(const float2*)(resp + r1 * ldc + col);
                    v0 += q0.x; v1 += q0.y; v2 += q1.x; v3 += q1.y;
                }
                if (ROUND) {
                    v0 = rnd_tf32(v0); v1 = rnd_tf32(v1);
                    v2 = rnd_tf32(v2); v3 = rnd_tf32(v3);
                }
                *(float2*)(C + r0 * ldc + col) = make_float2(v0, v1);
                *(float2*)(C + r1 * ldc + col) = make_float2(v2, v3);
            }
        }
    } else {
        __syncthreads();
#pragma unroll
        for (int mt = 0; mt < 4; ++mt) {
            const int rl0 = wm + mt * 16 + g;
#pragma unroll
            for (int nt = 0; nt < 8; ++nt) {
                const int cl = wn + nt * 8 + 2 * q;
                *(float2*)&smem[rl0 * 136 + cl] =
                    make_float2(acc[mt][nt][0] * alpha, acc[mt][nt][1] * alpha);
                *(float2*)&smem[(rl0 + 8) * 136 + cl] =
                    make_float2(acc[mt][nt][2] * alpha, acc[mt][nt][3] * alpha);
            }
        }
        __syncthreads();
        const int col = tid;                        // 128 cols
        float* crow = C + (n0 + col) * (long long)ldc + m0;
#pragma unroll
        for (int j = 0; j < 32; ++j) {
            const int rb = j * 4;
            float4 v;
            v.x = smem[(rb + 0) * 136 + col];
            v.y = smem[(rb + 1) * 136 + col];
            v.z = smem[(rb + 2) * 136 + col];
            v.w = smem[(rb + 3) * 136 + col];
            if (ROUND) {
                v.x = rnd_tf32(v.x); v.y = rnd_tf32(v.y);
                v.z = rnd_tf32(v.z); v.w = rnd_tf32(v.w);
            }
            *(float4*)(crow + rb) = v;
        }
    }
}

// ---------------------------------------------------------------------------
// transpose + tf32-round: out[n][k] = rnd(in[k][n]), 1024x1024
// ---------------------------------------------------------------------------
__global__ __launch_bounds__(256)
void transpose_round(const float* __restrict__ in, float* __restrict__ out)
{
    __shared__ float t[32][33];
    const int tx = threadIdx.x & 31, ty = threadIdx.x >> 5;
    const int bx = blockIdx.x * 32, by = blockIdx.y * 32;
#pragma unroll
    for (int j = 0; j < 32; j += 8)
        t[ty + j][tx] = in[(long long)(by + ty + j) * D_MODEL + bx + tx];
    __syncthreads();
#pragma unroll
    for (int j = 0; j < 32; j += 8)
        out[(long long)(bx + ty + j) * D_MODEL + by + tx] = rnd_tf32(t[tx][ty + j]);
}

__global__ __launch_bounds__(256)
void embed_kernel(const int* __restrict__ x, const float* __restrict__ enc,
                  float* __restrict__ z)
{
    const int row = blockIdx.x;
    const float4* s = (const float4*)(enc + (long long)x[row] * D_MODEL);
    float4* d = (float4*)(z + (long long)row * D_MODEL);
    d[threadIdx.x] = s[threadIdx.x];
}

// "LayerNorm" (faithful buggy): y = (x - mu/sqrt(var)) * g + b, ddof=1; tf32 out
__global__ __launch_bounds__(256)
void ln_kernel(const float* __restrict__ x, float* __restrict__ y,
               const float* __restrict__ g, const float* __restrict__ b)
{
    const int row = blockIdx.x;
    const float4 v = ((const float4*)(x + (long long)row * D_MODEL))[threadIdx.x];
    float s  = v.x + v.y + v.z + v.w;
    float s2 = v.x * v.x + v.y * v.y + v.z * v.z + v.w * v.w;
#pragma unroll
    for (int o = 16; o; o >>= 1) {
        s  += __shfl_down_sync(0xffffffffu, s, o);
        s2 += __shfl_down_sync(0xffffffffu, s2, o);
    }
    __shared__ float shs[8], shs2[8], shsub;
    const int w = threadIdx.x >> 5, l = threadIdx.x & 31;
    if (l == 0) { shs[w] = s; shs2[w] = s2; }
    __syncthreads();
    if (threadIdx.x == 0) {
        float ts = 0.f, ts2 = 0.f;
#pragma unroll
        for (int i = 0; i < 8; ++i) { ts += shs[i]; ts2 += shs2[i]; }
        const float mu  = ts / (float)D_MODEL;
        const float var = (ts2 - (float)D_MODEL * mu * mu) / (float)(D_MODEL - 1);
        shsub = mu * rsqrtf(var);
    }
    __syncthreads();
    const float sub = shsub;
    const float4 gg = ((const float4*)g)[threadIdx.x];
    const float4 bb = ((const float4*)b)[threadIdx.x];
    float4 o4;
    o4.x = rnd_tf32((v.x - sub) * gg.x + bb.x);
    o4.y = rnd_tf32((v.y - sub) * gg.y + bb.y);
    o4.z = rnd_tf32((v.z - sub) * gg.z + bb.z);
    o4.w = rnd_tf32((v.w - sub) * gg.w + bb.w);
    ((float4*)(y + (long long)row * D_MODEL))[threadIdx.x] = o4;
}

__global__ __launch_bounds__(256)
void softmax_kernel(float* __restrict__ s)
{
    float4* r4 = (float4*)(s + (long long)blockIdx.x * SEQ_T);
    float4 v = r4[threadIdx.x];
    float m = fmaxf(fmaxf(v.x, v.y), fmaxf(v.z, v.w));
#pragma unroll
    for (int o = 16; o; o >>= 1) m = fmaxf(m, __shfl_down_sync(0xffffffffu, m, o));
    __shared__ float shm[8], shsum[8], shM, shS;
    const int w = threadIdx.x >> 5, l = threadIdx.x & 31;
    if (l == 0) shm[w] = m;
    __syncthreads();
    if (threadIdx.x == 0) {
        float t = shm[0];
#pragma unroll
        for (int i = 1; i < 8; ++i) t = fmaxf(t, shm[i]);
        shM = t;
    }
    __syncthreads();
    const float M = shM;
    v.x = __expf(v.x - M); v.y = __expf(v.y - M);
    v.z = __expf(v.z - M); v.w = __expf(v.w - M);
    float sum = v.x + v.y + v.z + v.w;
#pragma unroll
    for (int o = 16; o; o >>= 1) sum += __shfl_down_sync(0xffffffffu, sum, o);
    if (l == 0) shsum[w] = sum;
    __syncthreads();
    if (threadIdx.x == 0) {
        float t = 0.f;
#pragma unroll
        for (int i = 0; i < 8; ++i) t += shsum[i];
        shS = 1.f / t;
    }
    __syncthreads();
    const float inv = shS;
    v.x = rnd_tf32(v.x * inv); v.y = rnd_tf32(v.y * inv);
    v.z = rnd_tf32(v.z * inv); v.w = rnd_tf32(v.w * inv);
    r4[threadIdx.x] = v;
}

// single-pass online logsumexp NLL
__global__ __launch_bounds__(256)
void nll_kernel(const float* __restrict__ logits, const int* __restrict__ y,
                float* __restrict__ nll)
{
    const int row = blockIdx.x;
    const float* r = logits + (long long)row * VOCAB;
    float m = -1e30f, s = 0.f;
    for (int i = threadIdx.x; i < VOCAB; i += 256) {
        const float v = r[i];
        if (v > m) { s = s * __expf(m - v) + 1.f; m = v; }
        else       { s += __expf(v - m); }
    }
#pragma unroll
    for (int o = 16; o; o >>= 1) {
        const float m2 = __shfl_down_sync(0xffffffffu, m, o);
        const float s2 = __shfl_down_sync(0xffffffffu, s, o);
        const float M = fmaxf(m, m2);
        s = s * __expf(m - M) + s2 * __expf(m2 - M);
        m = M;
    }
    __shared__ float shm[8], shs[8];
    const int w = threadIdx.x >> 5, l = threadIdx.x & 31;
    if (l == 0) { shm[w] = m; shs[w] = s; }
    __syncthreads();
    if (threadIdx.x == 0) {
        float M = shm[0], S = shs[0];
#pragma unroll
        for (int i = 1; i < 8; ++i) {
            const float MM = fmaxf(M, shm[i]);
            S = S * __expf(M - MM) + shs[i] * __expf(shm[i] - MM);
            M = MM;
        }
        nll[row] = logf(S) + M - r[y[row]];
    }
}

__global__ __launch_bounds__(256)
void loss_kernel(const float* __restrict__ nll, float* __restrict__ out,
                 long long out_elems)
{
    __shared__ float sh[256];
    float s = 0.f;
#pragma unroll
    for (int u = 0; u < ROWS / 256; ++u) s += nll[threadIdx.x + u * 256];
    sh[threadIdx.x] = s;
    __syncthreads();
    for (int stride = 128; stride > 0; stride >>= 1) {
        if (threadIdx.x < stride) sh[threadIdx.x] += sh[threadIdx.x + stride];
        __syncthreads();
    }
    if (threadIdx.x == 0 && out_elems > LOGITS_ELEMS)
        out[LOGITS_ELEMS] = sh[0] / (float)ROWS;
}

// ---------------------------------------------------------------------------
extern "C" void kernel_launch(void* const* d_in, const int* in_sizes, int n_in,
                              void* d_out, int out_size)
{
    const int*   x   = (const int*)  d_in[0];
    const int*   ytk = (const int*)  d_in[1];
    const float* enc = (const float*)d_in[2];
    const float* g1  = (const float*)d_in[3];
    const float* b1  = (const float*)d_in[4];
    const float* wq  = (const float*)d_in[5];
    const float* wk  = (const float*)d_in[6];
    const float* wv  = (const float*)d_in[7];
    const float* g2  = (const float*)d_in[8];
    const float* b2  = (const float*)d_in[9];
    const float* w1  = (const float*)d_in[10];
    const float* bb1 = (const float*)d_in[11];
    const float* w2  = (const float*)d_in[12];
    const float* bb2 = (const float*)d_in[13];
    float* out = (float*)d_out;

    float *z, *y, *q, *k, *vT, *s, *h, *o, *nll;
    float *wqT, *wkT, *wvT, *w1T, *w2T;
    cudaGetSymbolAddress((void**)&z,   g_z);
    cudaGetSymbolAddress((void**)&y,   g_y);
    cudaGetSymbolAddress((void**)&q,   g_q);
    cudaGetSymbolAddress((void**)&k,   g_k);
    cudaGetSymbolAddress((void**)&vT,  g_vT);
    cudaGetSymbolAddress((void**)&s,   g_s);
    cudaGetSymbolAddress((void**)&h,   g_h);
    cudaGetSymbolAddress((void**)&o,   g_o);
    cudaGetSymbolAddress((void**)&nll, g_nll);
    cudaGetSymbolAddress((void**)&wqT, g_wqT);
    cudaGetSymbolAddress((void**)&wkT, g_wkT);
    cudaGetSymbolAddress((void**)&wvT, g_wvT);
    cudaGetSymbolAddress((void**)&w1T, g_w1T);
    cudaGetSymbolAddress((void**)&w2T, g_w2T);

    cudaFuncSetAttribute(tgemm<false,false,false,true,false,false>,
        cudaFuncAttributeMaxDynamicSharedMemorySize, GEMM_SMEM_BYTES);
    cudaFuncSetAttribute(tgemm<false,false,false,true,true,false>,
        cudaFuncAttributeMaxDynamicSharedMemorySize, GEMM_SMEM_BYTES);
    cudaFuncSetAttribute(tgemm<false,false,false,false,false,false>,
        cudaFuncAttributeMaxDynamicSharedMemorySize, GEMM_SMEM_BYTES);
    cudaFuncSetAttribute(tgemm<true,true,false,true,false,false>,
        cudaFuncAttributeMaxDynamicSharedMemorySize, GEMM_SMEM_BYTES);
    cudaFuncSetAttribute(tgemm<true,false,true,false,false,false>,
        cudaFuncAttributeMaxDynamicSharedMemorySize, GEMM_SMEM_BYTES);
    cudaFuncSetAttribute(tgemm<true,false,true,true,false,false>,
        cudaFuncAttributeMaxDynamicSharedMemorySize, GEMM_SMEM_BYTES);
    cudaFuncSetAttribute(tgemm<false,false,false,false,false,true>,
        cudaFuncAttributeMaxDynamicSharedMemorySize, GEMM_SMEM_BYTES);

    const long long TD = (long long)SEQ_T * D_MODEL;
    const long long TT = (long long)SEQ_T * SEQ_T;
    const float attn_scale = 1.f / 32.f;
    const int D = D_MODEL;

    const dim3 gT(32, 32);
    transpose_round<<<gT, 256>>>(wq, wqT);
    transpose_round<<<gT, 256>>>(wk, wkT);
    transpose_round<<<gT, 256>>>(wv, wvT);
    transpose_round<<<gT, 256>>>(w1, w1T);
    transpose_round<<<gT, 256>>>(w2, w2T);

    embed_kernel<<<ROWS, 256>>>(x, enc, z);

    const dim3 gMain(D_MODEL / 128, ROWS / 128);        // (8, 32)
    const dim3 gAttn(SEQ_T / 128, SEQ_T / 128, BATCH);  // (8, 8, 4)

    for (int layer = 0; layer < NLAYERS; ++layer) {
        ln_kernel<<<ROWS, 256>>>(z, y, g1, b1);
        tgemm<false,false,false,true,false,false><<<gMain, 128, GEMM_SMEM_BYTES>>>(
            y, wqT, q, nullptr, nullptr, D, D, D, D, 1.f, 0, 0, 0);
        tgemm<false,false,false,true,false,false><<<gMain, 128, GEMM_SMEM_BYTES>>>(
            y, wkT, k, nullptr, nullptr, D, D, D, D, 1.f, 0, 0, 0);
        tgemm<false,false,false,true,true,false><<<gMain, 128, GEMM_SMEM_BYTES>>>(
            y, wvT, vT, nullptr, nullptr, D, D, D, ROWS, 1.f, 0, 0, 0);
        tgemm<false,false,false,false,false,false><<<gAttn, 128, GEMM_SMEM_BYTES>>>(
            q, k, s, nullptr, nullptr, D, D, D, SEQ_T, attn_scale, TD, TD, TT);
        softmax_kernel<<<ROWS, 256>>>(s);
        tgemm<false,false,false,false,false,false><<<gAttn, 128, GEMM_SMEM_BYTES>>>(
            s, vT, o, nullptr, nullptr, SEQ_T, SEQ_T, ROWS, D, 1.f, TT, SEQ_T, TD);
        ln_kernel<<<ROWS, 256>>>(o, y, g2, b2);
        tgemm<true,true,false,true,false,false><<<gMain, 128, GEMM_SMEM_BYTES>>>(
            y, w1T, h, bb1, nullptr, D, D, D, D, 1.f, 0, 0, 0);
        if (layer < NLAYERS - 1) {
            tgemm<true,false,true,false,false,false><<<gMain, 128, GEMM_SMEM_BYTES>>>(
                h, w2T, z, bb2, z, D, D, D, D, 1.f, 0, 0, 0);
        } else {
            // final layer: rounded residual into y (logits A operand)
            tgemm<true,false,true,true,false,false><<<gMain, 128, GEMM_SMEM_BYTES>>>(
                h, w2T, y, bb2, z, D, D, D, D, 1.f, 0, 0, 0);
        }
    }

    // logits = round(z) @ enc^T, enc rounded in-GEMM (CVTB)
    const dim3 gLog(VOCAB / 128, ROWS / 128);           // (250, 32)
    tgemm<false,false,false,false,false,true><<<gLog, 128, GEMM_SMEM_BYTES>>>(
        y, enc, out, nullptr, nullptr, D, D, D, VOCAB, 1.f, 0, 0, 0);

    nll_kernel<<<ROWS, 256>>>(out, ytk, nll);
    loss_kernel<<<1, 256>>>(nll, out, (long long)out_size);
}

// round 10
// speedup vs baseline: 1.1612x; 1.1612x over previous
#include <cuda_runtime.h>
#include <math.h>
#include <stdint.h>

// ---------------------------------------------------------------------------
// NanoGPT forward — round 8: R6 GEMM config (256 thr, 64x32 warp tile) +
// CVTB logits (no enc rounding pass) + float4 LN/softmax.
// ---------------------------------------------------------------------------

#define D_MODEL 1024
#define SEQ_T   1024
#define BATCH   4
#define ROWS    (BATCH * SEQ_T)
#define VOCAB   32000
#define NLAYERS 6
#define LOGITS_ELEMS ((long long)ROWS * VOCAB)

// ---- scratch ----
__device__ float g_z[ROWS * D_MODEL];
__device__ float g_y[ROWS * D_MODEL];
__device__ float g_q[ROWS * D_MODEL];
__device__ float g_k[ROWS * D_MODEL];
__device__ float g_vT[D_MODEL * ROWS];          // v transposed: [d][b*T+t]
__device__ float g_s[BATCH * SEQ_T * SEQ_T];
__device__ float g_h[ROWS * D_MODEL];
__device__ float g_o[ROWS * D_MODEL];
__device__ float g_nll[ROWS];
__device__ float g_wqT[D_MODEL * D_MODEL];
__device__ float g_wkT[D_MODEL * D_MODEL];
__device__ float g_wvT[D_MODEL * D_MODEL];
__device__ float g_w1T[D_MODEL * D_MODEL];
__device__ float g_w2T[D_MODEL * D_MODEL];

__device__ __forceinline__ float rnd_tf32(float x) {
    uint32_t u;
    asm("cvt.rna.tf32.f32 %0, %1;" : "=r"(u) : "f"(x));
    return __uint_as_float(u);
}
__device__ __forceinline__ uint32_t cvt_bits(uint32_t x) {
    uint32_t u;
    asm("cvt.rna.tf32.f32 %0, %1;" : "=r"(u) : "f"(__uint_as_float(x)));
    return u;
}

__device__ __forceinline__ void mma_tf32(float c[4], const uint32_t a[4],
                                         const uint32_t b[2]) {
    asm volatile(
        "mma.sync.aligned.m16n8k8.row.col.f32.tf32.tf32.f32 "
        "{%0,%1,%2,%3}, {%4,%5,%6,%7}, {%8,%9}, {%0,%1,%2,%3};\n"
        : "+f"(c[0]), "+f"(c[1]), "+f"(c[2]), "+f"(c[3])
        : "r"(a[0]), "r"(a[1]), "r"(a[2]), "r"(a[3]), "r"(b[0]), "r"(b[1]));
}

__device__ __forceinline__ void ldsm4(uint32_t r[4], uint32_t addr) {
    asm volatile("ldmatrix.sync.aligned.m8n8.x4.shared.b16 {%0,%1,%2,%3}, [%4];"
                 : "=r"(r[0]), "=r"(r[1]), "=r"(r[2]), "=r"(r[3]) : "r"(addr));
}

__device__ __forceinline__ void cpa16s(uint32_t saddr, const float* g) {
    asm volatile("cp.async.cg.shared.global [%0], [%1], 16;\n" :: "r"(saddr), "l"(g));
}

#define STAGES 3
#define STAGE_WORDS 9216                 // A 128*36 + B 128*36
#define GEMM_SMEM_BYTES (STAGES * STAGE_WORDS * 4)   // 110592, > 128*136*4

// ---------------------------------------------------------------------------
// tf32 tensor GEMM, NT only: C[M,N] = alpha * A[M,K] @ B[N,K]^T.
// A ld=lda, B ld=ldb (K-contiguous; A pre-rounded tf32; B pre-rounded unless
// CVTB, then B fragments rounded post-LDSM).
// Block 128x128x32, 256 thr, 8 warps (2m x 4n), warp tile 64x32.
// 3-stage cp.async ring; fragments via ldmatrix.x4.
// TRANS: writes C^T via smem-staged transpose (C[col][row], ld=ldc).
// ---------------------------------------------------------------------------
template <bool BIAS, bool RELU, bool RES, bool ROUND, bool TRANS, bool CVTB>
__global__ __launch_bounds__(256, 2)
void tgemm(const float* __restrict__ A, const float* __restrict__ B,
           float* __restrict__ C, const float* __restrict__ bias,
           const float* __restrict__ res,
           int K, int lda, int ldb, int ldc, float alpha,
           long long sA, long long sB, long long sC)
{
    extern __shared__ float smem[];

    A += (long long)blockIdx.z * sA;
    B += (long long)blockIdx.z * sB;
    C += (long long)blockIdx.z * sC;
    const float* resp = RES ? (res + (long long)blockIdx.z * sC) : nullptr;

    const int tid  = threadIdx.x;
    const int lane = tid & 31;
    const int warp = tid >> 5;
    const int wm   = (warp & 1) * 64;
    const int wn   = (warp >> 1) * 32;
    const int q    = lane & 3;
    const int g    = lane >> 2;
    const long long m0 = (long long)blockIdx.y * 128;
    const long long n0 = (long long)blockIdx.x * 128;

    const uint32_t smem_u = (uint32_t)__cvta_generic_to_shared(smem);

    // producer map: 4 rows of A + 4 rows of B per thread (float4 chunks)
    const int prow = tid >> 3;          // +32*s
    const int pk4  = (tid & 7) * 4;

    // ldmatrix per-lane word offsets (within a stage)
    const uint32_t aw = (uint32_t)((wm + (lane & 15)) * 36 + ((lane >> 4) & 1) * 4);
    const uint32_t bw = (uint32_t)(4608 +
        (wn + ((lane >> 4) & 1) * 8 + (lane & 7)) * 36 + ((lane >> 3) & 1) * 4);

    float acc[4][4][4];
#pragma unroll
    for (int mt = 0; mt < 4; ++mt)
#pragma unroll
        for (int nt = 0; nt < 4; ++nt)
#pragma unroll
            for (int i = 0; i < 4; ++i) acc[mt][nt][i] = 0.f;

    auto LOAD = [&](int stage, int k0) {
        const uint32_t sb = smem_u + stage * (STAGE_WORDS * 4);
#pragma unroll
        for (int s = 0; s < 4; ++s)
            cpa16s(sb + ((prow + 32 * s) * 36 + pk4) * 4,
                   A + (m0 + prow + 32 * s) * (long long)lda + k0 + pk4);
#pragma unroll
        for (int s = 0; s < 4; ++s)
            cpa16s(sb + (4608 + (prow + 32 * s) * 36 + pk4) * 4,
                   B + (n0 + prow + 32 * s) * (long long)ldb + k0 + pk4);
    };

    auto COMP = [&](int stage) {
        const uint32_t sb = smem_u + stage * (STAGE_WORDS * 4);
#pragma unroll
        for (int kb = 0; kb < 4; ++kb) {
            uint32_t af[4][4], bf[4][2];
#pragma unroll
            for (int mt = 0; mt < 4; ++mt)
                ldsm4(af[mt], sb + (aw + mt * 576 + kb * 8) * 4);
#pragma unroll
            for (int tp = 0; tp < 2; ++tp) {
                uint32_t r[4];
                ldsm4(r, sb + (bw + tp * 576 + kb * 8) * 4);
                if (CVTB) {
                    r[0] = cvt_bits(r[0]); r[1] = cvt_bits(r[1]);
                    r[2] = cvt_bits(r[2]); r[3] = cvt_bits(r[3]);
                }
                bf[tp * 2][0] = r[0]; bf[tp * 2][1] = r[1];
                bf[tp * 2 + 1][0] = r[2]; bf[tp * 2 + 1][1] = r[3];
            }
#pragma unroll
            for (int mt = 0; mt < 4; ++mt)
#pragma unroll
                for (int nt = 0; nt < 4; ++nt)
                    mma_tf32(acc[mt][nt], af[mt], bf[nt]);
        }
    };

    const int T = K >> 5;
    LOAD(0, 0);
    asm volatile("cp.async.commit_group;\n");
    if (T > 1) LOAD(1, 32);
    asm volatile("cp.async.commit_group;\n");

    int st = 0;
    for (int i = 0; i < T; ++i) {
        asm volatile("cp.async.wait_group 1;\n");
        __syncthreads();
        if (i + 2 < T) {
            int ns = st + 2; if (ns >= STAGES) ns -= STAGES;
            LOAD(ns, (i + 2) << 5);
        }
        asm volatile("cp.async.commit_group;\n");
        COMP(st);
        if (++st == STAGES) st = 0;
    }

    // ---- epilogue ----
    if (!TRANS) {
#pragma unroll
        for (int mt = 0; mt < 4; ++mt) {
            const long long r0 = m0 + wm + mt * 16 + g;
            const long long r1 = r0 + 8;
#pragma unroll
            for (int nt = 0; nt < 4; ++nt) {
                const long long col = n0 + wn + nt * 8 + 2 * q;
                float v0 = acc[mt][nt][0] * alpha;
                float v1 = acc[mt][nt][1] * alpha;
                float v2 = acc[mt][nt][2] * alpha;
                float v3 = acc[mt][nt][3] * alpha;
                if (BIAS) {
                    const float bb0 = bias[col], bb1 = bias[col + 1];
                    v0 += bb0; v1 += bb1; v2 += bb0; v3 += bb1;
                }
                if (RELU) {
                    v0 = fmaxf(v0, 0.f); v1 = fmaxf(v1, 0.f);
                    v2 = fmaxf(v2, 0.f); v3 = fmaxf(v3, 0.f);
                }
                if (RES) {
                    const float2 q0 = *(const float2*)(resp + r0 * ldc + col);
                    const float2 q1 = *(const float2*)(resp + r1 * ldc + col);
                    v0 += q0.x; v1 += q0.y; v2 += q1.x; v3 += q1.y;
                }
                if (ROUND) {
                    v0 = rnd_tf32(v0); v1 = rnd_tf32(v1);
                    v2 = rnd_tf32(v2); v3 = rnd_tf32(v3);
                }
                *(float2*)(C + r0 * ldc + col) = make_float2(v0, v1);
                *(float2*)(C + r1 * ldc + col) = make_float2(v2, v3);
            }
        }
    } else {
        // stage into smem [128][136], then coalesced transposed store
        __syncthreads();
#pragma unroll
        for (int mt = 0; mt < 4; ++mt) {
            const int rl0 = wm + mt * 16 + g;
#pragma unroll
            for (int nt = 0; nt < 4; ++nt) {
                const int cl = wn + nt * 8 + 2 * q;
                *(float2*)&smem[rl0 * 136 + cl] =
                    make_float2(acc[mt][nt][0] * alpha, acc[mt][nt][1] * alpha);
                *(float2*)&smem[(rl0 + 8) * 136 + cl] =
                    make_float2(acc[mt][nt][2] * alpha, acc[mt][nt][3] * alpha);
            }
        }
        __syncthreads();
        const int col  = tid & 127;
        const int half = tid >> 7;          // 0/1 -> 64-row halves
        float* crow = C + (n0 + col) * (long long)ldc + m0 + half * 64;
#pragma unroll
        for (int j = 0; j < 16; ++j) {
            const int rb = half * 64 + j * 4;
            float4 v;
            v.x = smem[(rb + 0) * 136 + col];
            v.y = smem[(rb + 1) * 136 + col];
            v.z = smem[(rb + 2) * 136 + col];
            v.w = smem[(rb + 3) * 136 + col];
            if (ROUND) {
                v.x = rnd_tf32(v.x); v.y = rnd_tf32(v.y);
                v.z = rnd_tf32(v.z); v.w = rnd_tf32(v.w);
            }
            *(float4*)(crow + j * 4) = v;
        }
    }
}

// ---------------------------------------------------------------------------
// transpose + tf32-round: out[n][k] = rnd(in[k][n]), 1024x1024
// ---------------------------------------------------------------------------
__global__ __launch_bounds__(256)
void transpose_round(const float* __restrict__ in, float* __restrict__ out)
{
    __shared__ float t[32][33];
    const int tx = threadIdx.x & 31, ty = threadIdx.x >> 5;
    const int bx = blockIdx.x * 32, by = blockIdx.y * 32;
#pragma unroll
    for (int j = 0; j < 32; j += 8)
        t[ty + j][tx] = in[(long long)(by + ty + j) * D_MODEL + bx + tx];
    __syncthreads();
#pragma unroll
    for (int j = 0; j < 32; j += 8)
        out[(long long)(bx + ty + j) * D_MODEL + by + tx] = rnd_tf32(t[tx][ty + j]);
}

__global__ __launch_bounds__(256)
void embed_kernel(const int* __restrict__ x, const float* __restrict__ enc,
                  float* __restrict__ z)
{
    const int row = blockIdx.x;
    const float4* s = (const float4*)(enc + (long long)x[row] * D_MODEL);
    float4* d = (float4*)(z + (long long)row * D_MODEL);
    d[threadIdx.x] = s[threadIdx.x];
}

// "LayerNorm" (faithful buggy): y = (x - mu/sqrt(var)) * g + b, ddof=1; tf32 out
__global__ __launch_bounds__(256)
void ln_kernel(const float* __restrict__ x, float* __restrict__ y,
               const float* __restrict__ g, const float* __restrict__ b)
{
    const int row = blockIdx.x;
    const float4 v = ((const float4*)(x + (long long)row * D_MODEL))[threadIdx.x];
    float s  = v.x + v.y + v.z + v.w;
    float s2 = v.x * v.x + v.y * v.y + v.z * v.z + v.w * v.w;
#pragma unroll
    for (int o = 16; o; o >>= 1) {
        s  += __shfl_down_sync(0xffffffffu, s, o);
        s2 += __shfl_down_sync(0xffffffffu, s2, o);
    }
    __shared__ float shs[8], shs2[8], shsub;
    const int w = threadIdx.x >> 5, l = threadIdx.x & 31;
    if (l == 0) { shs[w] = s; shs2[w] = s2; }
    __syncthreads();
    if (threadIdx.x == 0) {
        float ts = 0.f, ts2 = 0.f;
#pragma unroll
        for (int i = 0; i < 8; ++i) { ts += shs[i]; ts2 += shs2[i]; }
        const float mu  = ts / (float)D_MODEL;
        const float var = (ts2 - (float)D_MODEL * mu * mu) / (float)(D_MODEL - 1);
        shsub = mu * rsqrtf(var);
    }
    __syncthreads();
    const float sub = shsub;
    const float4 gg = ((const float4*)g)[threadIdx.x];
    const float4 bb = ((const float4*)b)[threadIdx.x];
    float4 o4;
    o4.x = rnd_tf32((v.x - sub) * gg.x + bb.x);
    o4.y = rnd_tf32((v.y - sub) * gg.y + bb.y);
    o4.z = rnd_tf32((v.z - sub) * gg.z + bb.z);
    o4.w = rnd_tf32((v.w - sub) * gg.w + bb.w);
    ((float4*)(y + (long long)row * D_MODEL))[threadIdx.x] = o4;
}

__global__ __launch_bounds__(256)
void softmax_kernel(float* __restrict__ s)
{
    float4* r4 = (float4*)(s + (long long)blockIdx.x * SEQ_T);
    float4 v = r4[threadIdx.x];
    float m = fmaxf(fmaxf(v.x, v.y), fmaxf(v.z, v.w));
#pragma unroll
    for (int o = 16; o; o >>= 1) m = fmaxf(m, __shfl_down_sync(0xffffffffu, m, o));
    __shared__ float shm[8], shsum[8], shM, shS;
    const int w = threadIdx.x >> 5, l = threadIdx.x & 31;
    if (l == 0) shm[w] = m;
    __syncthreads();
    if (threadIdx.x == 0) {
        float t = shm[0];
#pragma unroll
        for (int i = 1; i < 8; ++i) t = fmaxf(t, shm[i]);
        shM = t;
    }
    __syncthreads();
    const float M = shM;
    v.x = __expf(v.x - M); v.y = __expf(v.y - M);
    v.z = __expf(v.z - M); v.w = __expf(v.w - M);
    float sum = v.x + v.y + v.z + v.w;
#pragma unroll
    for (int o = 16; o; o >>= 1) sum += __shfl_down_sync(0xffffffffu, sum, o);
    if (l == 0) shsum[w] = sum;
    __syncthreads();
    if (threadIdx.x == 0) {
        float t = 0.f;
#pragma unroll
        for (int i = 0; i < 8; ++i) t += shsum[i];
        shS = 1.f / t;
    }
    __syncthreads();
    const float inv = shS;
    v.x = rnd_tf32(v.x * inv); v.y = rnd_tf32(v.y * inv);
    v.z = rnd_tf32(v.z * inv); v.w = rnd_tf32(v.w * inv);
    r4[threadIdx.x] = v;
}

// single-pass online logsumexp NLL
__global__ __launch_bounds__(256)
void nll_kernel(const float* __restrict__ logits, const int* __restrict__ y,
                float* __restrict__ nll)
{
    const int row = blockIdx.x;
    const float* r = logits + (long long)row * VOCAB;
    float m = -1e30f, s = 0.f;
    for (int i = threadIdx.x; i < VOCAB; i += 256) {
        const float v = r[i];
        if (v > m) { s = s * __expf(m - v) + 1.f; m = v; }
        else       { s += __expf(v - m); }
    }
#pragma unroll
    for (int o = 16; o; o >>= 1) {
        const float m2 = __shfl_down_sync(0xffffffffu, m, o);
        const float s2 = __shfl_down_sync(0xffffffffu, s, o);
        const float M = fmaxf(m, m2);
        s = s * __expf(m - M) + s2 * __expf(m2 - M);
        m = M;
    }
    __shared__ float shm[8], shs[8];
    const int w = threadIdx.x >> 5, l = threadIdx.x & 31;
    if (l == 0) { shm[w] = m; shs[w] = s; }
    __syncthreads();
    if (threadIdx.x == 0) {
        float M = shm[0], S = shs[0];
#pragma unroll
        for (int i = 1; i < 8; ++i) {
            const float MM = fmaxf(M, shm[i]);
            S = S * __expf(M - MM) + shs[i] * __expf(shm[i] - MM);
            M = MM;
        }
        nll[row] = logf(S) + M - r[y[row]];
    }
}

__global__ __launch_bounds__(256)
void loss_kernel(const float* __restrict__ nll, float* __restrict__ out,
                 long long out_elems)
{
    __shared__ float sh[256];
    float s = 0.f;
#pragma unroll
    for (int u = 0; u < ROWS / 256; ++u) s += nll[threadIdx.x + u * 256];
    sh[threadIdx.x] = s;
    __syncthreads();
    for (int stride = 128; stride > 0; stride >>= 1) {
        if (threadIdx.x < stride) sh[threadIdx.x] += sh[threadIdx.x + stride];
        __syncthreads();
    }
    if (threadIdx.x == 0 && out_elems > LOGITS_ELEMS)
        out[LOGITS_ELEMS] = sh[0] / (float)ROWS;
}

// ---------------------------------------------------------------------------
extern "C" void kernel_launch(void* const* d_in, const int* in_sizes, int n_in,
                              void* d_out, int out_size)
{
    const int*   x   = (const int*)  d_in[0];
    const int*   ytk = (const int*)  d_in[1];
    const float* enc = (const float*)d_in[2];
    const float* g1  = (const float*)d_in[3];
    const float* b1  = (const float*)d_in[4];
    const float* wq  = (const float*)d_in[5];
    const float* wk  = (const float*)d_in[6];
    const float* wv  = (const float*)d_in[7];
    const float* g2  = (const float*)d_in[8];
    const float* b2  = (const float*)d_in[9];
    const float* w1  = (const float*)d_in[10];
    const float* bb1 = (const float*)d_in[11];
    const float* w2  = (const float*)d_in[12];
    const float* bb2 = (const float*)d_in[13];
    float* out = (float*)d_out;

    float *z, *y, *q, *k, *vT, *s, *h, *o, *nll;
    float *wqT, *wkT, *wvT, *w1T, *w2T;
    cudaGetSymbolAddress((void**)&z,   g_z);
    cudaGetSymbolAddress((void**)&y,   g_y);
    cudaGetSymbolAddress((void**)&q,   g_q);
    cudaGetSymbolAddress((void**)&k,   g_k);
    cudaGetSymbolAddress((void**)&vT,  g_vT);
    cudaGetSymbolAddress((void**)&s,   g_s);
    cudaGetSymbolAddress((void**)&h,   g_h);
    cudaGetSymbolAddress((void**)&o,   g_o);
    cudaGetSymbolAddress((void**)&nll, g_nll);
    cudaGetSymbolAddress((void**)&wqT, g_wqT);
    cudaGetSymbolAddress((void**)&wkT, g_wkT);
    cudaGetSymbolAddress((void**)&wvT, g_wvT);
    cudaGetSymbolAddress((void**)&w1T, g_w1T);
    cudaGetSymbolAddress((void**)&w2T, g_w2T);

    cudaFuncSetAttribute(tgemm<false,false,false,true,false,false>,
        cudaFuncAttributeMaxDynamicSharedMemorySize, GEMM_SMEM_BYTES);
    cudaFuncSetAttribute(tgemm<false,false,false,true,true,false>,
        cudaFuncAttributeMaxDynamicSharedMemorySize, GEMM_SMEM_BYTES);
    cudaFuncSetAttribute(tgemm<false,false,false,false,false,false>,
        cudaFuncAttributeMaxDynamicSharedMemorySize, GEMM_SMEM_BYTES);
    cudaFuncSetAttribute(tgemm<true,true,false,true,false,false>,
        cudaFuncAttributeMaxDynamicSharedMemorySize, GEMM_SMEM_BYTES);
    cudaFuncSetAttribute(tgemm<true,false,true,false,false,false>,
        cudaFuncAttributeMaxDynamicSharedMemorySize, GEMM_SMEM_BYTES);
    cudaFuncSetAttribute(tgemm<true,false,true,true,false,false>,
        cudaFuncAttributeMaxDynamicSharedMemorySize, GEMM_SMEM_BYTES);
    cudaFuncSetAttribute(tgemm<false,false,false,false,false,true>,
        cudaFuncAttributeMaxDynamicSharedMemorySize, GEMM_SMEM_BYTES);

    const long long TD = (long long)SEQ_T * D_MODEL;
    const long long TT = (long long)SEQ_T * SEQ_T;
    const float attn_scale = 1.f / 32.f;
    const int D = D_MODEL;

    const dim3 gT(32, 32);
    transpose_round<<<gT, 256>>>(wq, wqT);
    transpose_round<<<gT, 256>>>(wk, wkT);
    transpose_round<<<gT, 256>>>(wv, wvT);
    transpose_round<<<gT, 256>>>(w1, w1T);
    transpose_round<<<gT, 256>>>(w2, w2T);

    embed_kernel<<<ROWS, 256>>>(x, enc, z);

    const dim3 gMain(D_MODEL / 128, ROWS / 128);        // (8, 32)
    const dim3 gAttn(SEQ_T / 128, SEQ_T / 128, BATCH);  // (8, 8, 4)

    for (int layer = 0; layer < NLAYERS; ++layer) {
        ln_kernel<<<ROWS, 256>>>(z, y, g1, b1);
        tgemm<false,false,false,true,false,false><<<gMain, 256, GEMM_SMEM_BYTES>>>(
            y, wqT, q, nullptr, nullptr, D, D, D, D, 1.f, 0, 0, 0);
        tgemm<false,false,false,true,false,false><<<gMain, 256, GEMM_SMEM_BYTES>>>(
            y, wkT, k, nullptr, nullptr, D, D, D, D, 1.f, 0, 0, 0);
        // vT[d][row] = (y @ wv)^T, rounded
        tgemm<false,false,false,true,true,false><<<gMain, 256, GEMM_SMEM_BYTES>>>(
            y, wvT, vT, nullptr, nullptr, D, D, D, ROWS, 1.f, 0, 0, 0);
        // s = q k^T / 32 per batch
        tgemm<false,false,false,false,false,false><<<gAttn, 256, GEMM_SMEM_BYTES>>>(
            q, k, s, nullptr, nullptr, D, D, D, SEQ_T, attn_scale, TD, TD, TT);
        softmax_kernel<<<ROWS, 256>>>(s);
        // o = s @ v : NT with B = vT batch slice (ld = ROWS)
        tgemm<false,false,false,false,false,false><<<gAttn, 256, GEMM_SMEM_BYTES>>>(
            s, vT, o, nullptr, nullptr, SEQ_T, SEQ_T, ROWS, D, 1.f, TT, SEQ_T, TD);
        ln_kernel<<<ROWS, 256>>>(o, y, g2, b2);
        tgemm<true,true,false,true,false,false><<<gMain, 256, GEMM_SMEM_BYTES>>>(
            y, w1T, h, bb1, nullptr, D, D, D, D, 1.f, 0, 0, 0);
        if (layer < NLAYERS - 1) {
            tgemm<true,false,true,false,false,false><<<gMain, 256, GEMM_SMEM_BYTES>>>(
                h, w2T, z, bb2, z, D, D, D, D, 1.f, 0, 0, 0);
        } else {
            // final layer: rounded residual into y (logits A operand)
            tgemm<true,false,true,true,false,false><<<gMain, 256, GEMM_SMEM_BYTES>>>(
                h, w2T, y, bb2, z, D, D, D, D, 1.f, 0, 0, 0);
        }
    }

    // logits = round(z) @ enc^T, enc rounded in-GEMM (CVTB)
    const dim3 gLog(VOCAB / 128, ROWS / 128);           // (250, 32)
    tgemm<false,false,false,false,false,true><<<gLog, 256, GEMM_SMEM_BYTES>>>(
        y, enc, out, nullptr, nullptr, D, D, D, VOCAB, 1.f, 0, 0, 0);

    nll_kernel<<<ROWS, 256>>>(out, ytk, nll);
    loss_kernel<<<1, 256>>>(nll, out, (long long)out_size);
}